// round 3
// baseline (speedup 1.0000x reference)
#include <cuda_runtime.h>

// Spalize: out[k][c][h][w] = img[c][h][w] * (mask[h][w] == k), k in [0,50),
// plus the mask appended (as float) if out_size covers it.
//
// HBM-write-bound (~157MB f32 out, write-once). All output stores are
// streaming (__stcs, evict-first) so L2 drains eagerly instead of holding
// ~100MB dirty at kernel end. Each thread handles 2 quads (8 pixels) for
// more store-level parallelism; KSPLIT=5 keeps the same 2560-block grid.

#define KCH 50
#define CCH 3
#define KSPLIT 5
#define KCHUNK (KCH / KSPLIT)   // 10

__device__ __forceinline__ int detect_is64(const int* __restrict__ mask) {
    const int lane = threadIdx.x & 31;
    const int w1 = __ldg(&mask[2 * lane + 1]);
    const int w2 = __ldg(&mask[2 * (lane + 32) + 1]);
    const unsigned b = __ballot_sync(0xffffffffu, (w1 | w2) == 0);
    return b == 0xffffffffu;
}

__device__ __forceinline__ void load_mask_quad(const int* __restrict__ mask,
                                               int q, int is64,
                                               int& m0, int& m1, int& m2, int& m3) {
    if (is64) {
        const int base = q * 8;   // 4 int64s; low word at even idx
        m0 = mask[base + 0]; m1 = mask[base + 2];
        m2 = mask[base + 4]; m3 = mask[base + 6];
    } else {
        const int4 mm = reinterpret_cast<const int4*>(mask)[q];
        m0 = mm.x; m1 = mm.y; m2 = mm.z; m3 = mm.w;
    }
}

__device__ __forceinline__ float4 sel4(float4 ic, int m0, int m1, int m2, int m3, int k) {
    float4 v;
    v.x = (m0 == k) ? ic.x : 0.0f;
    v.y = (m1 == k) ? ic.y : 0.0f;
    v.z = (m2 == k) ? ic.z : 0.0f;
    v.w = (m3 == k) ? ic.w : 0.0f;
    return v;
}

__global__ void __launch_bounds__(256) spalize_fused_kernel(
    const float* __restrict__ img,
    const int*   __restrict__ mask,
    float*       __restrict__ out,
    int nq,            // HW/4 quads total
    int nblocksQ,      // number of q-blocks (each covers 512 quads = 2/thread)
    int nSpalBlocks)   // nblocksQ * KSPLIT
{
    const int is64 = detect_is64(mask);

    if (blockIdx.x >= nSpalBlocks) {
        // ---- mask tail: out[n_img + i] = (float)mask[i], 8 per thread ----
        const int tb = blockIdx.x - nSpalBlocks;
        const int q0 = (tb * blockDim.x + threadIdx.x) * 2;
        const long long n_img4 = (long long)KCH * CCH * nq;  // float4 units
        #pragma unroll
        for (int j = 0; j < 2; j++) {
            const int q = q0 + j;
            if (q < nq) {
                int m0, m1, m2, m3;
                load_mask_quad(mask, q, is64, m0, m1, m2, m3);
                float4 v = make_float4((float)m0, (float)m1, (float)m2, (float)m3);
                __stcs(&reinterpret_cast<float4*>(out)[n_img4 + q], v);
            }
        }
        return;
    }

    // ---- spalize: 2 quads per thread ----
    const int qb = blockIdx.x % nblocksQ;
    const int ks = blockIdx.x / nblocksQ;
    const int qA = (qb * blockDim.x + threadIdx.x) * 2;
    const int qB = qA + 1;
    if (qA >= nq) return;

    int a0, a1, a2, a3, b0, b1, b2, b3;
    load_mask_quad(mask, qA, is64, a0, a1, a2, a3);
    load_mask_quad(mask, qB, is64, b0, b1, b2, b3);

    const float4* img4 = reinterpret_cast<const float4*>(img);
    float4 iA0 = img4[0 * nq + qA], iB0 = img4[0 * nq + qB];
    float4 iA1 = img4[1 * nq + qA], iB1 = img4[1 * nq + qB];
    float4 iA2 = img4[2 * nq + qA], iB2 = img4[2 * nq + qB];

    float4* out4 = reinterpret_cast<float4*>(out);
    const int k0 = ks * KCHUNK;

    #pragma unroll
    for (int kk = 0; kk < KCHUNK; kk++) {
        const int k = k0 + kk;
        const long long obase = (long long)(k * CCH) * nq;
        __stcs(&out4[obase + 0LL * nq + qA], sel4(iA0, a0, a1, a2, a3, k));
        __stcs(&out4[obase + 0LL * nq + qB], sel4(iB0, b0, b1, b2, b3, k));
        __stcs(&out4[obase + 1LL * nq + qA], sel4(iA1, a0, a1, a2, a3, k));
        __stcs(&out4[obase + 1LL * nq + qB], sel4(iB1, b0, b1, b2, b3, k));
        __stcs(&out4[obase + 2LL * nq + qA], sel4(iA2, a0, a1, a2, a3, k));
        __stcs(&out4[obase + 2LL * nq + qB], sel4(iB2, b0, b1, b2, b3, k));
    }
}

extern "C" void kernel_launch(void* const* d_in, const int* in_sizes, int n_in,
                              void* d_out, int out_size)
{
    const float* img  = (const float*)d_in[0];
    const int*   mask = (const int*)d_in[1];
    float*       out  = (float*)d_out;

    const int HW = in_sizes[0] / CCH;       // 512*512
    const int nq = HW >> 2;                 // 65536 quads

    const int threads     = 256;
    const int quadsPerBlk = threads * 2;                         // 512
    const int nblocksQ    = (nq + quadsPerBlk - 1) / quadsPerBlk; // 128
    const int nSpalBlocks = nblocksQ * KSPLIT;                    // 640... see grid

    const long long n_img = (long long)KCH * CCH * HW;
    const bool wantTail = ((long long)out_size >= n_img + HW);
    const int grid = nSpalBlocks + (wantTail ? nblocksQ : 0);

    spalize_fused_kernel<<<grid, threads>>>(img, mask, out, nq, nblocksQ, nSpalBlocks);
}

// round 5
// speedup vs baseline: 2.7960x; 2.7960x over previous
#include <cuda_runtime.h>

// Spalize: out[k][c][h][w] = img[c][h][w] * (mask[h][w] == k), k in [0,50),
// plus the mask appended (as float) if out_size covers it.
//
// R2 geometry (fully-coalesced: 1 quad/thread, KSPLIT=10, 2816 blocks)
// + single delta: streaming stores (__stcs) on the write-once output so
// L2 drains eagerly instead of holding ~100MB dirty at kernel end.

#define KCH 50
#define CCH 3
#define KSPLIT 10
#define KCHUNK (KCH / KSPLIT)   // 5

__device__ __forceinline__ int detect_is64(const int* __restrict__ mask) {
    const int lane = threadIdx.x & 31;
    const int w1 = __ldg(&mask[2 * lane + 1]);
    const int w2 = __ldg(&mask[2 * (lane + 32) + 1]);
    const unsigned b = __ballot_sync(0xffffffffu, (w1 | w2) == 0);
    return b == 0xffffffffu;
}

__device__ __forceinline__ void load_mask_quad(const int* __restrict__ mask,
                                               int q, int is64,
                                               int& m0, int& m1, int& m2, int& m3) {
    if (is64) {
        const int base = q * 8;   // 4 int64s; low word at even idx
        m0 = mask[base + 0]; m1 = mask[base + 2];
        m2 = mask[base + 4]; m3 = mask[base + 6];
    } else {
        const int4 mm = reinterpret_cast<const int4*>(mask)[q];
        m0 = mm.x; m1 = mm.y; m2 = mm.z; m3 = mm.w;
    }
}

__device__ __forceinline__ float4 sel4(float4 ic, int m0, int m1, int m2, int m3, int k) {
    float4 v;
    v.x = (m0 == k) ? ic.x : 0.0f;
    v.y = (m1 == k) ? ic.y : 0.0f;
    v.z = (m2 == k) ? ic.z : 0.0f;
    v.w = (m3 == k) ? ic.w : 0.0f;
    return v;
}

__global__ void __launch_bounds__(256) spalize_fused_kernel(
    const float* __restrict__ img,
    const int*   __restrict__ mask,
    float*       __restrict__ out,
    int nq,            // HW/4
    int nblocksQ,      // ceil(nq/256)
    int nSpalBlocks)   // nblocksQ * KSPLIT
{
    const int is64 = detect_is64(mask);

    if (blockIdx.x >= nSpalBlocks) {
        // ---- mask tail: out[n_img + i] = (float)mask[i], 4 per thread ----
        const int tb = blockIdx.x - nSpalBlocks;
        const int q  = tb * blockDim.x + threadIdx.x;
        if (q < nq) {
            int m0, m1, m2, m3;
            load_mask_quad(mask, q, is64, m0, m1, m2, m3);
            float4 v = make_float4((float)m0, (float)m1, (float)m2, (float)m3);
            const long long n_img4 = (long long)KCH * CCH * nq;  // float4 units
            __stcs(&reinterpret_cast<float4*>(out)[n_img4 + q], v);
        }
        return;
    }

    // ---- spalize: 1 quad per thread, lanes contiguous ----
    const int qb = blockIdx.x % nblocksQ;
    const int ks = blockIdx.x / nblocksQ;
    const int q  = qb * blockDim.x + threadIdx.x;
    if (q >= nq) return;

    int m0, m1, m2, m3;
    load_mask_quad(mask, q, is64, m0, m1, m2, m3);

    const float4* img4 = reinterpret_cast<const float4*>(img);
    float4 ic0 = img4[0 * nq + q];
    float4 ic1 = img4[1 * nq + q];
    float4 ic2 = img4[2 * nq + q];

    float4* out4 = reinterpret_cast<float4*>(out);
    const int k0 = ks * KCHUNK;

    #pragma unroll
    for (int kk = 0; kk < KCHUNK; kk++) {
        const int k = k0 + kk;
        const long long obase = (long long)(k * CCH) * nq + q;
        __stcs(&out4[obase + 0LL * nq], sel4(ic0, m0, m1, m2, m3, k));
        __stcs(&out4[obase + 1LL * nq], sel4(ic1, m0, m1, m2, m3, k));
        __stcs(&out4[obase + 2LL * nq], sel4(ic2, m0, m1, m2, m3, k));
    }
}

extern "C" void kernel_launch(void* const* d_in, const int* in_sizes, int n_in,
                              void* d_out, int out_size)
{
    const float* img  = (const float*)d_in[0];
    const int*   mask = (const int*)d_in[1];
    float*       out  = (float*)d_out;

    const int HW = in_sizes[0] / CCH;       // 512*512
    const int nq = HW >> 2;                 // 65536

    const int threads     = 256;
    const int nblocksQ    = (nq + threads - 1) / threads;   // 256
    const int nSpalBlocks = nblocksQ * KSPLIT;              // 2560

    const long long n_img = (long long)KCH * CCH * HW;
    const bool wantTail = ((long long)out_size >= n_img + HW);
    const int grid = nSpalBlocks + (wantTail ? nblocksQ : 0);

    spalize_fused_kernel<<<grid, threads>>>(img, mask, out, nq, nblocksQ, nSpalBlocks);
}